// round 17
// baseline (speedup 1.0000x reference)
#include <cuda_runtime.h>
#include <cuda_bf16.h>
#include <cstdint>

__device__ double             g_total = 0.0;
__device__ unsigned long long g_rows  = 0ull;
__device__ unsigned int       g_done  = 0u;

#define CAP      192
#define MAXL     1024
#define OVF_CAP  4096
__device__ int      d_cnt[MAXL];            // statically zero; reset by B's last block
__device__ int      d_bucket[MAXL * CAP];
__device__ int      d_ovf_cnt = 0;
__device__ unsigned d_ovf[OVF_CAP];

#define THREADS 256

// Packed f32x2 FMA (sm_103a FFMA2 — PTX-only).
__device__ __forceinline__ unsigned long long fma2(unsigned long long a,
                                                   unsigned long long b,
                                                   unsigned long long c)
{
    unsigned long long d;
    asm("fma.rn.f32x2 %0, %1, %2, %3;" : "=l"(d) : "l"(a), "l"(b), "l"(c));
    return d;
}

__device__ __forceinline__ float unpack_sum(unsigned long long v)
{
    return __int_as_float((int)(v & 0xFFFFFFFFull)) +
           __int_as_float((int)(v >> 32));
}

struct U4 { unsigned long long a, b, c, d; };

// 32B load, L2 evict-last (sm_103: modifier requires 256-bit width).
__device__ __forceinline__ U4 ldg_el(const void* p)
{
    U4 v;
    asm("ld.global.L2::evict_last.v4.b64 {%0, %1, %2, %3}, [%4];"
        : "=l"(v.a), "=l"(v.b), "=l"(v.c), "=l"(v.d) : "l"(p));
    return v;
}

// ---------------- Kernel A: bucket active rows by label ----------------
__global__ __launch_bounds__(THREADS)
void bucket_kernel(const int* __restrict__ labels,
                   const int* __restrict__ num_old_p,
                   int batch)
{
    const int num_old = *num_old_p;
    const int r = blockIdx.x * THREADS + threadIdx.x;
    if (r < batch) {
        const int l = labels[r];
        if (l < num_old) {
            const int pos = atomicAdd(&d_cnt[l], 1);
            if (pos < CAP) {
                d_bucket[l * CAP + pos] = r;
            } else {
                const int o = atomicAdd(&d_ovf_cnt, 1);
                if (o < OVF_CAP)
                    d_ovf[o] = (unsigned)r | ((unsigned)l << 16);
            }
        }
    }
}

// ---------------- Kernel B: label-major MSE ----------------
// 2 blocks per label. Thread owns a fixed 32B column slice; centroid slice
// lives in registers for the whole block -> centroid L2 traffic ~2MB total.
__global__ __launch_bounds__(THREADS, 5)
void mse_kernel(const float* __restrict__ emb,
                const float* __restrict__ cen,
                float* __restrict__ out,
                int ncls)
{
    const int      l      = blockIdx.x >> 1;
    const int      half   = blockIdx.x & 1;
    const unsigned tid    = threadIdx.x;
    const unsigned lane   = tid & 31u;
    const unsigned rowslt = tid >> 6;            // 0..3: 4 rows in parallel
    const unsigned colB   = (tid & 63u) * 32u;   // byte offset in the 2KB row

    const char* __restrict__ embB = reinterpret_cast<const char*>(emb);
    const char* __restrict__ cenB = reinterpret_cast<const char*>(cen);

    const unsigned long long NEG1 = 0xBF800000BF800000ull;
    unsigned long long accA = 0ull, accB = 0ull, accC = 0ull, accD = 0ull;

    const int n_all   = d_cnt[l];
    const int n_store = n_all < CAP ? n_all : CAP;
    const int lo      = half ? (n_store + 1) >> 1 : 0;
    const int hi      = half ? n_store : (n_store + 1) >> 1;

    if (hi > lo) {
        // Centroid slice for my column: loaded once, held in registers.
        const U4 cm = ldg_el(cenB + (size_t)l * 2048u + colB);

        const int* bkt = d_bucket + l * CAP;
        int k = lo + (int)rowslt;

        // Steady state: 2 rows per thread per iter, loads batched.
        for (; k + 4 < hi; k += 8) {
            const int r0 = bkt[k];          // warp-uniform (64-thread row group)
            const int r1 = bkt[k + 4];
            const U4 e0 = ldg_el(embB + (size_t)r0 * 2048u + colB);
            const U4 e1 = ldg_el(embB + (size_t)r1 * 2048u + colB);
            unsigned long long d;
            d = fma2(cm.a, NEG1, e0.a); accA = fma2(d, d, accA);
            d = fma2(cm.b, NEG1, e0.b); accB = fma2(d, d, accB);
            d = fma2(cm.c, NEG1, e0.c); accC = fma2(d, d, accC);
            d = fma2(cm.d, NEG1, e0.d); accD = fma2(d, d, accD);
            d = fma2(cm.a, NEG1, e1.a); accA = fma2(d, d, accA);
            d = fma2(cm.b, NEG1, e1.b); accB = fma2(d, d, accB);
            d = fma2(cm.c, NEG1, e1.c); accC = fma2(d, d, accC);
            d = fma2(cm.d, NEG1, e1.d); accD = fma2(d, d, accD);
        }
        // Remainder: at most one row per thread.
        for (; k < hi; k += 4) {
            const int r0 = bkt[k];
            const U4 e0 = ldg_el(embB + (size_t)r0 * 2048u + colB);
            unsigned long long d;
            d = fma2(cm.a, NEG1, e0.a); accA = fma2(d, d, accA);
            d = fma2(cm.b, NEG1, e0.b); accB = fma2(d, d, accB);
            d = fma2(cm.c, NEG1, e0.c); accC = fma2(d, d, accC);
            d = fma2(cm.d, NEG1, e0.d); accD = fma2(d, d, accD);
        }
    }

    // Overflow entries (essentially never populated; exactness fallback).
    {
        int ovf = d_ovf_cnt; if (ovf > OVF_CAP) ovf = OVF_CAP;
        if (rowslt == 0u) {   // 64 threads cover the full row width
            for (int o = blockIdx.x; o < ovf; o += gridDim.x) {
                const unsigned pk = d_ovf[o];
                const unsigned r  = pk & 0xFFFFu;
                const unsigned l2 = pk >> 16;
                const U4 e = ldg_el(embB + (size_t)r  * 2048u + colB);
                const U4 c = ldg_el(cenB + (size_t)l2 * 2048u + colB);
                unsigned long long d;
                d = fma2(c.a, NEG1, e.a); accA = fma2(d, d, accA);
                d = fma2(c.b, NEG1, e.b); accB = fma2(d, d, accB);
                d = fma2(c.c, NEG1, e.c); accC = fma2(d, d, accC);
                d = fma2(c.d, NEG1, e.d); accD = fma2(d, d, accD);
            }
        }
    }

    // ---- Reduction ----
    float acc = unpack_sum(accA) + unpack_sum(accB) +
                unpack_sum(accC) + unpack_sum(accD);
    #pragma unroll
    for (int off = 16; off > 0; off >>= 1)
        acc += __shfl_xor_sync(0xFFFFFFFFu, acc, off);

    __shared__ double s_total;
    if (tid == 0) s_total = 0.0;
    __syncthreads();
    if (lane == 0 && acc != 0.0f) atomicAdd(&s_total, (double)acc);
    __syncthreads();

    if (tid == 0) {
        if (s_total != 0.0) atomicAdd(&g_total, s_total);
        if (half == 0 && n_all > 0)
            atomicAdd(&g_rows, (unsigned long long)n_all);
        __threadfence();
        const unsigned ticket = atomicAdd(&g_done, 1u);
        if (ticket == gridDim.x - 1u) {
            const double             t = g_total * (1.0 / 512.0);
            const unsigned long long c = g_rows;
            out[0] = (c == 0ull) ? (float)t : (float)(t / (double)c);
            // Reset all state for the next graph replay.
            g_total = 0.0;
            g_rows  = 0ull;
            g_done  = 0u;
            d_ovf_cnt = 0;
            for (int j = 0; j < MAXL; j++) d_cnt[j] = 0;
        }
    }
}

extern "C" void kernel_launch(void* const* d_in, const int* in_sizes, int n_in,
                              void* d_out, int out_size)
{
    const float* emb       = (const float*)d_in[0];
    const float* cen       = (const float*)d_in[1];
    const int*   labels    = (const int*)d_in[2];
    const int*   num_old_p = (const int*)d_in[3];
    float*       out       = (float*)d_out;

    const int dim   = 512;
    const int batch = in_sizes[0] / dim;   // 65536
    const int ncls  = in_sizes[1] / dim;   // 1000

    bucket_kernel<<<(batch + THREADS - 1) / THREADS, THREADS>>>(labels, num_old_p, batch);
    mse_kernel<<<2 * ncls, THREADS>>>(emb, cen, out, ncls);
}